// round 11
// baseline (speedup 1.0000x reference)
#include <cuda_runtime.h>

// CorrTorch 3D correlation, max_displacement=1.
// in1, in2: [1, 64, 64, 128, 128] fp32; out: [1, 27, 64, 128, 128] fp32.
//
// R10 -> R11: deepen the software pipeline now that the loads are pinned.
// R10 confirmed the binding constraint is outstanding-load count (24 warps x
// MLP4 = 96 in flight -> every throughput at ~50%). 3-stage register ring
// doubles per-warp MLP (4 -> 8 outstanding). R6 tried this and ptxas
// collapsed the ring; R10's asm-volatile LDG.128s cannot be sunk/merged, so
// the ring must hold this time. launch_bounds(192,3): reg cap 128, expect
// ~100 regs, 18 warps/SM -> 144 loads in flight (+50%).

namespace {
constexpr int C  = 64;
constexpr int DD = 64;
constexpr int HH = 128;
constexpr int WW = 128;
constexpr int HW = HH * WW;        // 16384
constexpr int CS = DD * HW;        // 1048576
constexpr int TPX = 64;            // 2 warps in x, each = one full W row
constexpr int NBLK = DD * HH * (WW / 4) / TPX;   // 4096
}

__device__ __forceinline__ float4 ldg128(const float* p) {
    float4 v;
    asm volatile("ld.global.nc.v4.f32 {%0,%1,%2,%3}, [%4];"
                 : "=f"(v.x), "=f"(v.y), "=f"(v.z), "=f"(v.w)
                 : "l"(p));
    return v;
}

__device__ __forceinline__ float4 ldg128_pred(const float* p, int pred) {
    float4 v;
    asm volatile("{\n\t"
        ".reg .pred q;\n\t"
        "setp.ne.s32 q, %5, 0;\n\t"
        "mov.f32 %0, 0f00000000;\n\t"
        "mov.f32 %1, 0f00000000;\n\t"
        "mov.f32 %2, 0f00000000;\n\t"
        "mov.f32 %3, 0f00000000;\n\t"
        "@q ld.global.nc.v4.f32 {%0,%1,%2,%3}, [%4];\n\t"
        "}"
        : "=f"(v.x), "=f"(v.y), "=f"(v.z), "=f"(v.w)
        : "l"(p), "r"(pred));
    return v;
}

struct Acc {
    float d0[3][3];   // dx=0: out1..out3 per dy
    float X[3];       // dx=0: halo sum -> right neighbor's out0
    float d1[3][4];   // dx=1: out0..out3
    float d2[3][3];   // dx=2: out0..out2
    float Y[3];       // dx=2: halo sum -> left neighbor's out3
};

__device__ __forceinline__ void ld_stage(const float* __restrict__ q1,
                                         const float* __restrict__ q2,
                                         const int rv[3],
                                         float4& a, float4 rm[3])
{
    a = ldg128(q1);
#pragma unroll
    for (int dy = 0; dy < 3; dy++) {
        rm[dy] = ldg128_pred(q2 + dy * WW, rv[dy]);
    }
}

__device__ __forceinline__ void do_compute(const float4& a, const float4 rm[3],
                                           Acc& A)
{
    float an0 = __shfl_down_sync(0xffffffffu, a.x, 1);  // right lane's a0
    float ap3 = __shfl_up_sync  (0xffffffffu, a.w, 1);  // left lane's a3
#pragma unroll
    for (int dy = 0; dy < 3; dy++) {
        const float4 r = rm[dy];
        // dx = 1: out[j] = a[j] * r[j]
        A.d1[dy][0] = fmaf(a.x, r.x, A.d1[dy][0]);
        A.d1[dy][1] = fmaf(a.y, r.y, A.d1[dy][1]);
        A.d1[dy][2] = fmaf(a.z, r.z, A.d1[dy][2]);
        A.d1[dy][3] = fmaf(a.w, r.w, A.d1[dy][3]);
        // dx = 0: out[j] = a[j] * r[j-1], j=1..3; halo (j=0) deferred via X
        A.d0[dy][0] = fmaf(a.y, r.x, A.d0[dy][0]);
        A.d0[dy][1] = fmaf(a.z, r.y, A.d0[dy][1]);
        A.d0[dy][2] = fmaf(a.w, r.z, A.d0[dy][2]);
        A.X[dy]     = fmaf(an0, r.w, A.X[dy]);
        // dx = 2: out[j] = a[j] * r[j+1], j=0..2; halo (j=3) deferred via Y
        A.d2[dy][0] = fmaf(a.x, r.y, A.d2[dy][0]);
        A.d2[dy][1] = fmaf(a.y, r.z, A.d2[dy][1]);
        A.d2[dy][2] = fmaf(a.z, r.w, A.d2[dy][2]);
        A.Y[dy]     = fmaf(ap3, r.x, A.Y[dy]);
    }
}

__global__ void __launch_bounds__(TPX * 3, 3) corr3d_kernel(
    const float* __restrict__ in1,
    const float* __restrict__ in2,
    float* __restrict__ out)
{
    const int s  = blockIdx.x * TPX + threadIdx.x;  // strip id
    const int dz = threadIdx.y;                     // 0..2
    const int lane = threadIdx.x & 31;
    const int w0 = (s & 31) << 2;                   // 0,4,...,124
    const int h  = (s >> 5) & 127;
    const int d  = s >> 12;

    const int zp = d + dz - 1;                      // in2 source plane
    const int pz = (zp >= 0) && (zp < DD);
    const int rv[3] = { pz && (h > 0), pz, pz && (h < HH - 1) };
    const bool pw0 = (lane > 0);
    const bool pw5 = (lane < 31);

    const float* q1 = in1 + d * HW + h * WW + w0;
    const float* q2 = in2 + zp * HW + (h - 1) * WW + w0;

    Acc A;
#pragma unroll
    for (int dy = 0; dy < 3; dy++) {
        A.d0[dy][0] = A.d0[dy][1] = A.d0[dy][2] = 0.f;
        A.d1[dy][0] = A.d1[dy][1] = A.d1[dy][2] = A.d1[dy][3] = 0.f;
        A.d2[dy][0] = A.d2[dy][1] = A.d2[dy][2] = 0.f;
        A.X[dy] = 0.f; A.Y[dy] = 0.f;
    }

    float4 aS0, aS1, aS2;
    float4 rmS0[3], rmS1[3], rmS2[3];

    // 3-stage ring: loads run 2 channels ahead of compute.
    ld_stage(q1, q2, rv, aS0, rmS0);                // c = 0
    q1 += CS; q2 += CS;
    ld_stage(q1, q2, rv, aS1, rmS1);                // c = 1

    for (int c = 0; c < 60; c += 3) {
        q1 += CS; q2 += CS;
        ld_stage(q1, q2, rv, aS2, rmS2);            // c+2 in flight
        do_compute(aS0, rmS0, A);                   // consume c
        q1 += CS; q2 += CS;
        ld_stage(q1, q2, rv, aS0, rmS0);            // c+3 in flight
        do_compute(aS1, rmS1, A);                   // consume c+1
        q1 += CS; q2 += CS;
        ld_stage(q1, q2, rv, aS1, rmS1);            // c+4 in flight
        do_compute(aS2, rmS2, A);                   // consume c+2
    }
    // computed 0..59; stages hold S0=60, S1=61
    q1 += CS; q2 += CS;
    ld_stage(q1, q2, rv, aS2, rmS2);                // 62
    do_compute(aS0, rmS0, A);                       // 60
    q1 += CS; q2 += CS;
    ld_stage(q1, q2, rv, aS0, rmS0);                // 63
    do_compute(aS1, rmS1, A);                       // 61
    do_compute(aS2, rmS2, A);                       // 62
    do_compute(aS0, rmS0, A);                       // 63

    float* op = out + (long)(dz * 9) * CS + d * HW + h * WW + w0;
    const float inv = 1.0f / 64.0f;
#pragma unroll
    for (int dy = 0; dy < 3; dy++) {
        // dx = 0: out0 comes from the left neighbor's X
        float xin = __shfl_up_sync(0xffffffffu, A.X[dy], 1);
        float4 v0 = make_float4(pw0 ? xin * inv : 0.f,
                                A.d0[dy][0] * inv, A.d0[dy][1] * inv,
                                A.d0[dy][2] * inv);
        *reinterpret_cast<float4*>(op + (long)(dy * 3 + 0) * CS) = v0;
        // dx = 1
        float4 v1 = make_float4(A.d1[dy][0] * inv, A.d1[dy][1] * inv,
                                A.d1[dy][2] * inv, A.d1[dy][3] * inv);
        *reinterpret_cast<float4*>(op + (long)(dy * 3 + 1) * CS) = v1;
        // dx = 2: out3 comes from the right neighbor's Y
        float yin = __shfl_down_sync(0xffffffffu, A.Y[dy], 1);
        float4 v2 = make_float4(A.d2[dy][0] * inv, A.d2[dy][1] * inv,
                                A.d2[dy][2] * inv,
                                pw5 ? yin * inv : 0.f);
        *reinterpret_cast<float4*>(op + (long)(dy * 3 + 2) * CS) = v2;
    }
}

extern "C" void kernel_launch(void* const* d_in, const int* in_sizes, int n_in,
                              void* d_out, int out_size)
{
    const float* in1 = (const float*)d_in[0];
    const float* in2 = (const float*)d_in[1];
    float* out = (float*)d_out;
    (void)in_sizes; (void)n_in; (void)out_size;

    dim3 blk(TPX, 3);
    corr3d_kernel<<<NBLK, blk>>>(in1, in2, out);
}

// round 12
// speedup vs baseline: 1.0011x; 1.0011x over previous
#include <cuda_runtime.h>

// CorrTorch 3D correlation, max_displacement=1.
// in1, in2: [1, 64, 64, 128, 128] fp32; out: [1, 27, 64, 128, 128] fp32.
//
// R11 -> R12: reg-funded MLP is dead (R6/R7/R11 all failed); warps are the
// only working latency-hiding currency. This round combines the two
// individually-validated wins that were never tested together:
//   - R5's f32x2 + deferred-halo diet (correctness verified; ~33 issues/ch)
//   - R10's pinned asm-volatile 128-bit loads (kills the ptxas load-split
//     bloat that invalidated R5/R8's measured instruction counts)
// on the only pipeline depth that ever worked (2-stage), with block (32,3)
// and launch_bounds(96,9) -> 72-reg cap = 27 warps/SM.

namespace {
constexpr int C  = 64;
constexpr int DD = 64;
constexpr int HH = 128;
constexpr int WW = 128;
constexpr int HW = HH * WW;        // 16384
constexpr int CS = DD * HW;        // 1048576
constexpr int TPX = 32;            // one warp in x = one full W row
constexpr int NBLK = DD * HH * (WW / 4) / TPX;   // 8192
}

using u64 = unsigned long long;

__device__ __forceinline__ void fma2(u64& d, u64 a, u64 b) {
    asm("fma.rn.f32x2 %0, %1, %2, %0;" : "+l"(d) : "l"(a), "l"(b));
}
__device__ __forceinline__ u64 pack2(float lo, float hi) {
    u64 r; asm("mov.b64 %0, {%1, %2};" : "=l"(r) : "f"(lo), "f"(hi)); return r;
}
__device__ __forceinline__ float2 unpack2(u64 v) {
    float2 r; asm("mov.b64 {%0, %1}, %2;" : "=f"(r.x), "=f"(r.y) : "l"(v)); return r;
}

__device__ __forceinline__ ulonglong2 ldg128u(const float* p) {
    ulonglong2 v;
    asm volatile("ld.global.nc.v2.u64 {%0,%1}, [%2];"
                 : "=l"(v.x), "=l"(v.y) : "l"(p));
    return v;
}
__device__ __forceinline__ ulonglong2 ldg128u_pred(const float* p, int pred) {
    ulonglong2 v;
    asm volatile("{\n\t"
        ".reg .pred q;\n\t"
        "setp.ne.s32 q, %3, 0;\n\t"
        "mov.u64 %0, 0;\n\t"
        "mov.u64 %1, 0;\n\t"
        "@q ld.global.nc.v2.u64 {%0,%1}, [%2];\n\t"
        "}"
        : "=l"(v.x), "=l"(v.y) : "l"(p), "r"(pred));
    return v;
}

struct Acc {
    u64   d1a[3], d1b[3];   // dx=1: (out0,out1), (out2,out3)
    u64   d0m[3];           // dx=0: (out1,out2)
    float d0e[3];           // dx=0: out3
    float X[3];             // dx=0: halo sum -> right neighbor's out0
    u64   d2m[3];           // dx=2: (out1,out2)
    float d2e[3];           // dx=2: out0
    float Y[3];             // dx=2: halo sum -> left neighbor's out3
};

__device__ __forceinline__ void ld_stage(const float* __restrict__ q1,
                                         const float* __restrict__ q2,
                                         const int rv[3],
                                         ulonglong2& a2, ulonglong2 rm[3])
{
    a2 = ldg128u(q1);
#pragma unroll
    for (int dy = 0; dy < 3; dy++) {
        rm[dy] = ldg128u_pred(q2 + dy * WW, rv[dy]);
    }
}

__device__ __forceinline__ void do_compute(const ulonglong2& a2,
                                           const ulonglong2 rm[3], Acc& A)
{
    float2 aL = unpack2(a2.x);   // a0, a1
    float2 aH = unpack2(a2.y);   // a2, a3
    u64 A12 = pack2(aL.y, aH.x); // (a1, a2)
    float an0 = __shfl_down_sync(0xffffffffu, aL.x, 1);  // right lane's a0
    float ap3 = __shfl_up_sync  (0xffffffffu, aH.y, 1);  // left lane's a3
#pragma unroll
    for (int dy = 0; dy < 3; dy++) {
        float2 rL = unpack2(rm[dy].x);  // r0, r1
        float2 rH = unpack2(rm[dy].y);  // r2, r3
        fma2(A.d1a[dy], a2.x, rm[dy].x);            // dx=1, out0/1
        fma2(A.d1b[dy], a2.y, rm[dy].y);            // dx=1, out2/3
        fma2(A.d0m[dy], A12, rm[dy].x);             // dx=0, out1/2
        A.d0e[dy] = fmaf(aH.y, rH.x, A.d0e[dy]);    // dx=0, out3
        A.X[dy]   = fmaf(an0, rH.y, A.X[dy]);       // dx=0, deferred halo
        fma2(A.d2m[dy], A12, rm[dy].y);             // dx=2, out1/2
        A.d2e[dy] = fmaf(aL.x, rL.y, A.d2e[dy]);    // dx=2, out0
        A.Y[dy]   = fmaf(ap3, rL.x, A.Y[dy]);       // dx=2, deferred halo
    }
}

__global__ void __launch_bounds__(TPX * 3, 9) corr3d_kernel(
    const float* __restrict__ in1,
    const float* __restrict__ in2,
    float* __restrict__ out)
{
    const int s  = blockIdx.x * TPX + threadIdx.x;  // strip id
    const int dz = threadIdx.y;                     // 0..2
    const int lane = threadIdx.x & 31;
    const int w0 = (s & 31) << 2;                   // 0,4,...,124
    const int h  = (s >> 5) & 127;
    const int d  = s >> 12;

    const int zp = d + dz - 1;                      // in2 source plane
    const int pz = (zp >= 0) && (zp < DD);
    const int rv[3] = { pz && (h > 0), pz, pz && (h < HH - 1) };
    const bool pw0 = (lane > 0);
    const bool pw5 = (lane < 31);

    const float* q1 = in1 + d * HW + h * WW + w0;
    const float* q2 = in2 + zp * HW + (h - 1) * WW + w0;

    Acc A;
#pragma unroll
    for (int dy = 0; dy < 3; dy++) {
        A.d1a[dy] = 0; A.d1b[dy] = 0; A.d0m[dy] = 0; A.d2m[dy] = 0;
        A.d0e[dy] = 0.f; A.X[dy] = 0.f; A.d2e[dy] = 0.f; A.Y[dy] = 0.f;
    }

    ulonglong2 aA, aB;
    ulonglong2 rmA[3], rmB[3];

    ld_stage(q1, q2, rv, aA, rmA);                  // c = 0

#pragma unroll 2
    for (int c = 0; c < C - 2; c += 2) {
        q1 += CS; q2 += CS;
        ld_stage(q1, q2, rv, aB, rmB);              // c+1 in flight
        do_compute(aA, rmA, A);                     // consume c
        q1 += CS; q2 += CS;
        ld_stage(q1, q2, rv, aA, rmA);              // c+2 in flight
        do_compute(aB, rmB, A);                     // consume c+1
    }
    q1 += CS; q2 += CS;
    ld_stage(q1, q2, rv, aB, rmB);                  // c = C-1
    do_compute(aA, rmA, A);
    do_compute(aB, rmB, A);

    float* op = out + (long)(dz * 9) * CS + d * HW + h * WW + w0;
    const float inv = 1.0f / 64.0f;
#pragma unroll
    for (int dy = 0; dy < 3; dy++) {
        // dx = 0: out0 comes from the left neighbor's X
        float xin = __shfl_up_sync(0xffffffffu, A.X[dy], 1);
        float2 m0 = unpack2(A.d0m[dy]);
        float4 v0 = make_float4(pw0 ? xin * inv : 0.f,
                                m0.x * inv, m0.y * inv, A.d0e[dy] * inv);
        *reinterpret_cast<float4*>(op + (long)(dy * 3 + 0) * CS) = v0;
        // dx = 1
        float2 p1 = unpack2(A.d1a[dy]);
        float2 p2 = unpack2(A.d1b[dy]);
        float4 v1 = make_float4(p1.x * inv, p1.y * inv, p2.x * inv, p2.y * inv);
        *reinterpret_cast<float4*>(op + (long)(dy * 3 + 1) * CS) = v1;
        // dx = 2: out3 comes from the right neighbor's Y
        float yin = __shfl_down_sync(0xffffffffu, A.Y[dy], 1);
        float2 m2 = unpack2(A.d2m[dy]);
        float4 v2 = make_float4(A.d2e[dy] * inv, m2.x * inv, m2.y * inv,
                                pw5 ? yin * inv : 0.f);
        *reinterpret_cast<float4*>(op + (long)(dy * 3 + 2) * CS) = v2;
    }
}

extern "C" void kernel_launch(void* const* d_in, const int* in_sizes, int n_in,
                              void* d_out, int out_size)
{
    const float* in1 = (const float*)d_in[0];
    const float* in2 = (const float*)d_in[1];
    float* out = (float*)d_out;
    (void)in_sizes; (void)n_in; (void)out_size;

    dim3 blk(TPX, 3);
    corr3d_kernel<<<NBLK, blk>>>(in1, in2, out);
}

// round 13
// speedup vs baseline: 1.0451x; 1.0440x over previous
#include <cuda_runtime.h>

// CorrTorch 3D correlation, max_displacement=1.
// in1, in2: [1, 64, 64, 128, 128] fp32; out: [1, 27, 64, 128, 128] fp32.
//
// R12 -> R13: single-variable edit on R10 (the best kernel, 173.5us).
// R10's predicated load helper spent 6 issues per in2 row (setp + 4 zero-MOVs
// + guarded ld); the 12 zero-MOVs/channel ran unconditionally (alu pipe 16%).
// Since the row predicates are loop-invariant, a register never written by a
// guarded load stays zero forever -> zero the stage registers ONCE before the
// loop and use a sticky read-write predicated load (setp + @q ld only).
// Everything else identical to R10: 2-stage pipeline, (64,3)x192 blocks,
// launch_bounds(192,4), scalar FMAs, deferred-halo compute.

namespace {
constexpr int C  = 64;
constexpr int DD = 64;
constexpr int HH = 128;
constexpr int WW = 128;
constexpr int HW = HH * WW;        // 16384
constexpr int CS = DD * HW;        // 1048576
constexpr int TPX = 64;            // 2 warps in x, each = one full W row
constexpr int NBLK = DD * HH * (WW / 4) / TPX;   // 4096
}

__device__ __forceinline__ float4 ldg128(const float* p) {
    float4 v;
    asm volatile("ld.global.nc.v4.f32 {%0,%1,%2,%3}, [%4];"
                 : "=f"(v.x), "=f"(v.y), "=f"(v.z), "=f"(v.w)
                 : "l"(p));
    return v;
}

// Sticky predicated load: leaves v unchanged when pred==0 (v pre-zeroed once
// outside the loop; a false predicate is loop-invariant so v stays zero).
__device__ __forceinline__ void ldg128_sticky(float4& v, const float* p, int pred) {
    asm volatile("{\n\t"
        ".reg .pred q;\n\t"
        "setp.ne.s32 q, %5, 0;\n\t"
        "@q ld.global.nc.v4.f32 {%0,%1,%2,%3}, [%4];\n\t"
        "}"
        : "+f"(v.x), "+f"(v.y), "+f"(v.z), "+f"(v.w)
        : "l"(p), "r"(pred));
}

struct Acc {
    float d0[3][3];   // dx=0: out1..out3 per dy
    float X[3];       // dx=0: halo sum -> right neighbor's out0
    float d1[3][4];   // dx=1: out0..out3
    float d2[3][3];   // dx=2: out0..out2
    float Y[3];       // dx=2: halo sum -> left neighbor's out3
};

__device__ __forceinline__ void ld_stage(const float* __restrict__ q1,
                                         const float* __restrict__ q2,
                                         const int rv[3],
                                         float4& a, float4 rm[3])
{
    a = ldg128(q1);
#pragma unroll
    for (int dy = 0; dy < 3; dy++) {
        ldg128_sticky(rm[dy], q2 + dy * WW, rv[dy]);
    }
}

__device__ __forceinline__ void do_compute(const float4& a, const float4 rm[3],
                                           Acc& A)
{
    float an0 = __shfl_down_sync(0xffffffffu, a.x, 1);  // right lane's a0
    float ap3 = __shfl_up_sync  (0xffffffffu, a.w, 1);  // left lane's a3
#pragma unroll
    for (int dy = 0; dy < 3; dy++) {
        const float4 r = rm[dy];
        // dx = 1: out[j] = a[j] * r[j]
        A.d1[dy][0] = fmaf(a.x, r.x, A.d1[dy][0]);
        A.d1[dy][1] = fmaf(a.y, r.y, A.d1[dy][1]);
        A.d1[dy][2] = fmaf(a.z, r.z, A.d1[dy][2]);
        A.d1[dy][3] = fmaf(a.w, r.w, A.d1[dy][3]);
        // dx = 0: out[j] = a[j] * r[j-1], j=1..3; halo (j=0) deferred via X
        A.d0[dy][0] = fmaf(a.y, r.x, A.d0[dy][0]);
        A.d0[dy][1] = fmaf(a.z, r.y, A.d0[dy][1]);
        A.d0[dy][2] = fmaf(a.w, r.z, A.d0[dy][2]);
        A.X[dy]     = fmaf(an0, r.w, A.X[dy]);
        // dx = 2: out[j] = a[j] * r[j+1], j=0..2; halo (j=3) deferred via Y
        A.d2[dy][0] = fmaf(a.x, r.y, A.d2[dy][0]);
        A.d2[dy][1] = fmaf(a.y, r.z, A.d2[dy][1]);
        A.d2[dy][2] = fmaf(a.z, r.w, A.d2[dy][2]);
        A.Y[dy]     = fmaf(ap3, r.x, A.Y[dy]);
    }
}

__global__ void __launch_bounds__(TPX * 3, 4) corr3d_kernel(
    const float* __restrict__ in1,
    const float* __restrict__ in2,
    float* __restrict__ out)
{
    const int s  = blockIdx.x * TPX + threadIdx.x;  // strip id
    const int dz = threadIdx.y;                     // 0..2
    const int lane = threadIdx.x & 31;
    const int w0 = (s & 31) << 2;                   // 0,4,...,124
    const int h  = (s >> 5) & 127;
    const int d  = s >> 12;

    const int zp = d + dz - 1;                      // in2 source plane
    const int pz = (zp >= 0) && (zp < DD);
    const int rv[3] = { pz && (h > 0), pz, pz && (h < HH - 1) };
    const bool pw0 = (lane > 0);
    const bool pw5 = (lane < 31);

    const float* q1 = in1 + d * HW + h * WW + w0;
    const float* q2 = in2 + zp * HW + (h - 1) * WW + w0;

    Acc A;
#pragma unroll
    for (int dy = 0; dy < 3; dy++) {
        A.d0[dy][0] = A.d0[dy][1] = A.d0[dy][2] = 0.f;
        A.d1[dy][0] = A.d1[dy][1] = A.d1[dy][2] = A.d1[dy][3] = 0.f;
        A.d2[dy][0] = A.d2[dy][1] = A.d2[dy][2] = 0.f;
        A.X[dy] = 0.f; A.Y[dy] = 0.f;
    }

    float4 aA, aB;
    float4 rmA[3], rmB[3];
    // Sticky-zero init: registers of rows with a false (loop-invariant)
    // predicate are never touched by the guarded loads below.
#pragma unroll
    for (int dy = 0; dy < 3; dy++) {
        rmA[dy] = make_float4(0.f, 0.f, 0.f, 0.f);
        rmB[dy] = make_float4(0.f, 0.f, 0.f, 0.f);
    }

    ld_stage(q1, q2, rv, aA, rmA);                  // c = 0

#pragma unroll 2
    for (int c = 0; c < C - 2; c += 2) {
        q1 += CS; q2 += CS;
        ld_stage(q1, q2, rv, aB, rmB);              // c+1 in flight
        do_compute(aA, rmA, A);                     // consume c
        q1 += CS; q2 += CS;
        ld_stage(q1, q2, rv, aA, rmA);              // c+2 in flight
        do_compute(aB, rmB, A);                     // consume c+1
    }
    q1 += CS; q2 += CS;
    ld_stage(q1, q2, rv, aB, rmB);                  // c = C-1
    do_compute(aA, rmA, A);
    do_compute(aB, rmB, A);

    float* op = out + (long)(dz * 9) * CS + d * HW + h * WW + w0;
    const float inv = 1.0f / 64.0f;
#pragma unroll
    for (int dy = 0; dy < 3; dy++) {
        // dx = 0: out0 comes from the left neighbor's X
        float xin = __shfl_up_sync(0xffffffffu, A.X[dy], 1);
        float4 v0 = make_float4(pw0 ? xin * inv : 0.f,
                                A.d0[dy][0] * inv, A.d0[dy][1] * inv,
                                A.d0[dy][2] * inv);
        *reinterpret_cast<float4*>(op + (long)(dy * 3 + 0) * CS) = v0;
        // dx = 1
        float4 v1 = make_float4(A.d1[dy][0] * inv, A.d1[dy][1] * inv,
                                A.d1[dy][2] * inv, A.d1[dy][3] * inv);
        *reinterpret_cast<float4*>(op + (long)(dy * 3 + 1) * CS) = v1;
        // dx = 2: out3 comes from the right neighbor's Y
        float yin = __shfl_down_sync(0xffffffffu, A.Y[dy], 1);
        float4 v2 = make_float4(A.d2[dy][0] * inv, A.d2[dy][1] * inv,
                                A.d2[dy][2] * inv,
                                pw5 ? yin * inv : 0.f);
        *reinterpret_cast<float4*>(op + (long)(dy * 3 + 2) * CS) = v2;
    }
}

extern "C" void kernel_launch(void* const* d_in, const int* in_sizes, int n_in,
                              void* d_out, int out_size)
{
    const float* in1 = (const float*)d_in[0];
    const float* in2 = (const float*)d_in[1];
    float* out = (float*)d_out;
    (void)in_sizes; (void)n_in; (void)out_size;

    dim3 blk(TPX, 3);
    corr3d_kernel<<<NBLK, blk>>>(in1, in2, out);
}